// round 15
// baseline (speedup 1.0000x reference)
#include <cuda_runtime.h>
#include <cuda_bf16.h>
#include <cstdint>

// Sobel conv (cross-correlation, SAME zero padding) + sign-difference maps.
// Rolling-register, PAIRED-column ownership: lane k owns col pairs
// {w0+2k, w0+2k+1} and {w0+64+2k, w0+64+2k+1}. x loads LDG.64, y stores STG.64.
// ROW-BAND blocks: 8 warps of a block cover the full 1024-col width of one
// 32-row band (full output lines form in L2 before writeback).
// Distance-1 software prefetch: row j+1 is loaded before row j is consumed,
// so every load hides behind a full iteration of compute/stores.

#define IMG_W 1024
#define IMG_H 1024
#define RS 32            // output rows per block (and per warp)
#define NWARP 8          // warps per block = column strips
#define NT (NWARP * 32)
#define FULL 0xffffffffu

__device__ __forceinline__ float fsign(float v) {
    // +-1 with v's sign bit, zeroed when v==0 (handles -0). No NaNs in data.
    const float s = __uint_as_float((__float_as_uint(v) & 0x80000000u) | 0x3f800000u);
    return (v != 0.0f) ? s : 0.0f;
}

struct RowVals {
    float2 a, bv;        // owned pairs: cols 2k..2k+1 and 64+2k..64+2k+1
    float lf, rt1, rt2;  // strip-edge halo (lane0 / lane31 only)
};

__device__ __forceinline__ RowVals load_row(const float* __restrict__ xb, int j,
                                            int lane, bool lane0, bool lane31,
                                            bool has_l, bool has_r) {
    RowVals r;
    r.a = make_float2(0.f, 0.f); r.bv = make_float2(0.f, 0.f);
    r.lf = 0.f; r.rt1 = 0.f; r.rt2 = 0.f;
    if ((unsigned)j < (unsigned)IMG_H) {
        const float* row = xb + (size_t)j * IMG_W;
        r.a  = *reinterpret_cast<const float2*>(row + 2 * lane);
        r.bv = *reinterpret_cast<const float2*>(row + 64 + 2 * lane);
        if (lane0 && has_l) r.lf = row[-1];
        if (lane31 && has_r) {
            const float2 t2 = *reinterpret_cast<const float2*>(row + 128);
            r.rt1 = t2.x; r.rt2 = t2.y;
        }
    }
    return r;
}

// horizontal combos for one input row.
// hd[c] = x[c-1]-x[c+1], hs[c] = x[c-1]+2x[c]+x[c+1]; order: a.x,a.y,b.x,b.y
__device__ __forceinline__ void row_combos(const RowVals& rv, bool lane0, bool lane31,
                                           float hd[4], float hs[4], float& hdR) {
    float lA = __shfl_up_sync(FULL, rv.a.y, 1);    // col 2k-1
    float rA = __shfl_down_sync(FULL, rv.a.x, 1);  // col 2k+2
    float lB = __shfl_up_sync(FULL, rv.bv.y, 1);
    float rB = __shfl_down_sync(FULL, rv.bv.x, 1);
    const float bB0 = __shfl_sync(FULL, rv.bv.x, 0);   // col w0+64
    const float tA  = __shfl_sync(FULL, rv.a.y, 31);   // col w0+63
    if (lane0)  { lA = rv.lf; lB = tA; }
    if (lane31) { rA = bB0;  rB = rv.rt1; }
    hd[0] = lA - rv.a.y;    hd[1] = rv.a.x - rA;
    hd[2] = lB - rv.bv.y;   hd[3] = rv.bv.x - rB;
    hs[0] = fmaf(2.f, rv.a.x,  lA + rv.a.y);
    hs[1] = fmaf(2.f, rv.a.y,  rv.a.x + rA);
    hs[2] = fmaf(2.f, rv.bv.x, lB + rv.bv.y);
    hs[3] = fmaf(2.f, rv.bv.y, rv.bv.x + rB);
    hdR = rv.bv.y - rv.rt2;   // col w0+128 (valid on lane31)
}

__global__ __launch_bounds__(NT, 3)
void sobel_sign_kernel(const float* __restrict__ x,
                       float* __restrict__ y,
                       float* __restrict__ y0,
                       float* __restrict__ y1) {
    const int lane = threadIdx.x & 31;
    const int wid  = threadIdx.x >> 5;
    const int b    = blockIdx.z;
    const int w0   = wid * 128;            // warp = column strip (full width/block)
    const int r0   = blockIdx.x * RS;      // block = 32-row band
    const int co0  = 2 * lane;             // first owned col (within strip)
    const int co1  = 64 + 2 * lane;        // second owned col

    const float* __restrict__ xb = x + (size_t)b * IMG_H * IMG_W + w0;
    float* __restrict__ ybx = y + (size_t)b * 2 * IMG_H * IMG_W + w0;
    float* __restrict__ yby = ybx + (size_t)IMG_H * IMG_W;
    float* __restrict__ y0b = y0 + (size_t)b * (IMG_H - 1) * (IMG_W - 1) + w0;
    float* __restrict__ y1b = y1 + (size_t)b * (IMG_H - 1) * (IMG_W - 1) + w0;

    const bool lane0  = (lane == 0);
    const bool lane31 = (lane == 31);
    const bool has_l  = (w0 > 0);
    const bool has_r  = (w0 + 128 < IMG_W);
    const bool skip3  = lane31 && !has_r;   // col w0+127 == 1023 on last strip

    float hdP1[4], hdP2[4], hsP1[4], hsP2[4];
    float hdRP1, hdRP2;
    float sgyP[4] = {0, 0, 0, 0};

    // ---- prologue: rows r0-1 and r0 ----
    {
        RowVals rv = load_row(xb, r0 - 1, lane, lane0, lane31, has_l, has_r);
        row_combos(rv, lane0, lane31, hdP2, hsP2, hdRP2);
    }
    {
        RowVals rv = load_row(xb, r0, lane, lane0, lane31, has_l, has_r);
        row_combos(rv, lane0, lane31, hdP1, hsP1, hdRP1);
    }

    // distance-1 prefetch pipeline: nxt holds row r0+1+it at loop top
    RowVals nxt = load_row(xb, r0 + 1, lane, lane0, lane31, has_l, has_r);

    // ---- main: emit y,y0 at m=r0+it ; y1 at m-1 (it>=1) ----
    #pragma unroll 4
    for (int it = 0; it < RS; it++) {
        const RowVals rv = nxt;
        nxt = load_row(xb, r0 + 2 + it, lane, lane0, lane31, has_l, has_r);

        float hd[4], hs[4], hdR;
        row_combos(rv, lane0, lane31, hd, hs, hdR);

        const int m = r0 + it;
        float gy[4], sgy[4], gx[4], sgx[4];
        #pragma unroll
        for (int k = 0; k < 4; k++) {
            gy[k]  = hsP2[k] - hs[k];
            sgy[k] = fsign(gy[k]);
            gx[k]  = fmaf(2.f, hdP1[k], hdP2[k] + hd[k]);
            sgx[k] = fsign(gx[k]);
        }
        const float gxR = fmaf(2.f, hdRP1, hdRP2 + hdR);

        const unsigned ro = (unsigned)m * IMG_W;
        *reinterpret_cast<float2*>(ybx + ro + co0) = make_float2(gx[0], gx[1]);
        *reinterpret_cast<float2*>(ybx + ro + co1) = make_float2(gx[2], gx[3]);
        *reinterpret_cast<float2*>(yby + ro + co0) = make_float2(gy[0], gy[1]);
        *reinterpret_cast<float2*>(yby + ro + co1) = make_float2(gy[2], gy[3]);

        // neighbor signs for y0 (right neighbor of pair-second cols)
        float sxn1 = __shfl_down_sync(FULL, sgx[0], 1);   // col 2k+2
        float sxn3 = __shfl_down_sync(FULL, sgx[2], 1);   // col 64+2k+2
        const float nbB = __shfl_sync(FULL, sgx[2], 0);   // col w0+64
        if (lane31) { sxn1 = nbB; sxn3 = fsign(gxR); }

        if (m < IMG_H - 1) {
            const unsigned eo = (unsigned)m * (IMG_W - 1);
            y0b[eo + co0]     = sgx[0] - sgx[1];
            y0b[eo + co0 + 1] = sgx[1] - sxn1;
            y0b[eo + co1]     = sgx[2] - sgx[3];
            if (!skip3) y0b[eo + co1 + 1] = sgx[3] - sxn3;
        }
        if (it >= 1) {   // m-1 <= 1022 always here
            const unsigned eo = (unsigned)(m - 1) * (IMG_W - 1);
            y1b[eo + co0]     = sgyP[0] - sgy[0];
            y1b[eo + co0 + 1] = sgyP[1] - sgy[1];
            y1b[eo + co1]     = sgyP[2] - sgy[2];
            if (!skip3) y1b[eo + co1 + 1] = sgyP[3] - sgy[3];
        }
        #pragma unroll
        for (int k = 0; k < 4; k++) {
            sgyP[k] = sgy[k];
            hdP2[k] = hdP1[k]; hdP1[k] = hd[k];
            hsP2[k] = hsP1[k]; hsP1[k] = hs[k];
        }
        hdRP2 = hdRP1; hdRP1 = hdR;
    }

    // ---- epilogue: y1 row r0+RS-1 needs gy at row r0+RS ----
    // nxt already holds row r0+RS+1 from the final prefetch.
    {
        const int m1 = r0 + RS - 1;
        if (m1 < IMG_H - 1) {
            float hd[4], hs[4], hdR;
            row_combos(nxt, lane0, lane31, hd, hs, hdR);
            const unsigned eo = (unsigned)m1 * (IMG_W - 1);
            const float s0 = fsign(hsP2[0] - hs[0]);
            const float s1 = fsign(hsP2[1] - hs[1]);
            const float s2 = fsign(hsP2[2] - hs[2]);
            const float s3 = fsign(hsP2[3] - hs[3]);
            y1b[eo + co0]     = sgyP[0] - s0;
            y1b[eo + co0 + 1] = sgyP[1] - s1;
            y1b[eo + co1]     = sgyP[2] - s2;
            if (!skip3) y1b[eo + co1 + 1] = sgyP[3] - s3;
        }
    }
}

extern "C" void kernel_launch(void* const* d_in, const int* in_sizes, int n_in,
                              void* d_out, int out_size) {
    const float* x = (const float*)d_in[0];
    const int B = in_sizes[0] / (IMG_H * IMG_W);

    float* y  = (float*)d_out;
    float* y0 = y  + (size_t)B * 2 * IMG_H * IMG_W;
    float* y1 = y0 + (size_t)B * (IMG_H - 1) * (IMG_W - 1);

    dim3 block(NT, 1, 1);
    dim3 grid(IMG_H / RS, 1, B);    // 32 row-bands x 16 batches = 512 blocks
    sobel_sign_kernel<<<grid, block>>>(x, y, y0, y1);
}

// round 16
// speedup vs baseline: 1.2893x; 1.2893x over previous
#include <cuda_runtime.h>
#include <cuda_bf16.h>
#include <cstdint>

// Sobel conv (cross-correlation, SAME zero padding) + sign-difference maps.
// Rolling-register, PAIRED-column ownership: lane k owns col pairs
// {w0+2k, w0+2k+1} and {w0+64+2k, w0+64+2k+1}. x loads LDG.64, y stores STG.64.
// ROW-BAND blocks: 8 warps of a block cover the full 1024-col width of one
// 32-row band (full output lines form in L2 before writeback).
// 64 regs / 4 blocks/SM is the measured optimum; unroll 8 gives ptxas a wider
// scheduling window at unchanged register pressure.

#define IMG_W 1024
#define IMG_H 1024
#define RS 32            // output rows per block (and per warp)
#define NWARP 8          // warps per block = column strips
#define NT (NWARP * 32)
#define FULL 0xffffffffu

__device__ __forceinline__ float fsign(float v) {
    // +-1 with v's sign bit, zeroed when v==0 (handles -0). No NaNs in data.
    const float s = __uint_as_float((__float_as_uint(v) & 0x80000000u) | 0x3f800000u);
    return (v != 0.0f) ? s : 0.0f;
}

struct RowVals {
    float2 a, bv;        // owned pairs: cols 2k..2k+1 and 64+2k..64+2k+1
    float lf, rt1, rt2;  // strip-edge halo (lane0 / lane31 only)
};

__device__ __forceinline__ RowVals load_row(const float* __restrict__ xb, int j,
                                            int lane, bool lane0, bool lane31,
                                            bool has_l, bool has_r) {
    RowVals r;
    r.a = make_float2(0.f, 0.f); r.bv = make_float2(0.f, 0.f);
    r.lf = 0.f; r.rt1 = 0.f; r.rt2 = 0.f;
    if ((unsigned)j < (unsigned)IMG_H) {
        const float* row = xb + (size_t)j * IMG_W;
        r.a  = *reinterpret_cast<const float2*>(row + 2 * lane);
        r.bv = *reinterpret_cast<const float2*>(row + 64 + 2 * lane);
        if (lane0 && has_l) r.lf = row[-1];
        if (lane31 && has_r) {
            const float2 t2 = *reinterpret_cast<const float2*>(row + 128);
            r.rt1 = t2.x; r.rt2 = t2.y;
        }
    }
    return r;
}

// horizontal combos for one input row.
// hd[c] = x[c-1]-x[c+1], hs[c] = x[c-1]+2x[c]+x[c+1]; order: a.x,a.y,b.x,b.y
__device__ __forceinline__ void row_combos(const RowVals& rv, bool lane0, bool lane31,
                                           float hd[4], float hs[4], float& hdR) {
    float lA = __shfl_up_sync(FULL, rv.a.y, 1);    // col 2k-1
    float rA = __shfl_down_sync(FULL, rv.a.x, 1);  // col 2k+2
    float lB = __shfl_up_sync(FULL, rv.bv.y, 1);
    float rB = __shfl_down_sync(FULL, rv.bv.x, 1);
    const float bB0 = __shfl_sync(FULL, rv.bv.x, 0);   // col w0+64
    const float tA  = __shfl_sync(FULL, rv.a.y, 31);   // col w0+63
    if (lane0)  { lA = rv.lf; lB = tA; }
    if (lane31) { rA = bB0;  rB = rv.rt1; }
    hd[0] = lA - rv.a.y;    hd[1] = rv.a.x - rA;
    hd[2] = lB - rv.bv.y;   hd[3] = rv.bv.x - rB;
    hs[0] = fmaf(2.f, rv.a.x,  lA + rv.a.y);
    hs[1] = fmaf(2.f, rv.a.y,  rv.a.x + rA);
    hs[2] = fmaf(2.f, rv.bv.x, lB + rv.bv.y);
    hs[3] = fmaf(2.f, rv.bv.y, rv.bv.x + rB);
    hdR = rv.bv.y - rv.rt2;   // col w0+128 (valid on lane31)
}

__global__ __launch_bounds__(NT, 4)
void sobel_sign_kernel(const float* __restrict__ x,
                       float* __restrict__ y,
                       float* __restrict__ y0,
                       float* __restrict__ y1) {
    const int lane = threadIdx.x & 31;
    const int wid  = threadIdx.x >> 5;
    const int b    = blockIdx.z;
    const int w0   = wid * 128;            // warp = column strip (full width/block)
    const int r0   = blockIdx.x * RS;      // block = 32-row band
    const int co0  = 2 * lane;             // first owned col (within strip)
    const int co1  = 64 + 2 * lane;        // second owned col

    const float* __restrict__ xb = x + (size_t)b * IMG_H * IMG_W + w0;
    float* __restrict__ ybx = y + (size_t)b * 2 * IMG_H * IMG_W + w0;
    float* __restrict__ yby = ybx + (size_t)IMG_H * IMG_W;
    float* __restrict__ y0b = y0 + (size_t)b * (IMG_H - 1) * (IMG_W - 1) + w0;
    float* __restrict__ y1b = y1 + (size_t)b * (IMG_H - 1) * (IMG_W - 1) + w0;

    const bool lane0  = (lane == 0);
    const bool lane31 = (lane == 31);
    const bool has_l  = (w0 > 0);
    const bool has_r  = (w0 + 128 < IMG_W);
    const bool skip3  = lane31 && !has_r;   // col w0+127 == 1023 on last strip

    float hdP1[4], hdP2[4], hsP1[4], hsP2[4];
    float hdRP1, hdRP2;
    float sgyP[4] = {0, 0, 0, 0};

    // ---- prologue: rows r0-1 and r0 ----
    {
        RowVals rv = load_row(xb, r0 - 1, lane, lane0, lane31, has_l, has_r);
        row_combos(rv, lane0, lane31, hdP2, hsP2, hdRP2);
    }
    {
        RowVals rv = load_row(xb, r0, lane, lane0, lane31, has_l, has_r);
        row_combos(rv, lane0, lane31, hdP1, hsP1, hdRP1);
    }

    // ---- main: emit y,y0 at m=r0+it ; y1 at m-1 (it>=1) ----
    #pragma unroll 8
    for (int it = 0; it < RS; it++) {
        const int j = r0 + 1 + it;
        RowVals rv = load_row(xb, j, lane, lane0, lane31, has_l, has_r);
        float hd[4], hs[4], hdR;
        row_combos(rv, lane0, lane31, hd, hs, hdR);

        const int m = r0 + it;
        float gy[4], sgy[4], gx[4], sgx[4];
        #pragma unroll
        for (int k = 0; k < 4; k++) {
            gy[k]  = hsP2[k] - hs[k];
            sgy[k] = fsign(gy[k]);
            gx[k]  = fmaf(2.f, hdP1[k], hdP2[k] + hd[k]);
            sgx[k] = fsign(gx[k]);
        }
        const float gxR = fmaf(2.f, hdRP1, hdRP2 + hdR);

        const unsigned ro = (unsigned)m * IMG_W;
        *reinterpret_cast<float2*>(ybx + ro + co0) = make_float2(gx[0], gx[1]);
        *reinterpret_cast<float2*>(ybx + ro + co1) = make_float2(gx[2], gx[3]);
        *reinterpret_cast<float2*>(yby + ro + co0) = make_float2(gy[0], gy[1]);
        *reinterpret_cast<float2*>(yby + ro + co1) = make_float2(gy[2], gy[3]);

        // neighbor signs for y0 (right neighbor of pair-second cols)
        float sxn1 = __shfl_down_sync(FULL, sgx[0], 1);   // col 2k+2
        float sxn3 = __shfl_down_sync(FULL, sgx[2], 1);   // col 64+2k+2
        const float nbB = __shfl_sync(FULL, sgx[2], 0);   // col w0+64
        if (lane31) { sxn1 = nbB; sxn3 = fsign(gxR); }

        if (m < IMG_H - 1) {
            const unsigned eo = (unsigned)m * (IMG_W - 1);
            y0b[eo + co0]     = sgx[0] - sgx[1];
            y0b[eo + co0 + 1] = sgx[1] - sxn1;
            y0b[eo + co1]     = sgx[2] - sgx[3];
            if (!skip3) y0b[eo + co1 + 1] = sgx[3] - sxn3;
        }
        if (it >= 1) {   // m-1 <= 1022 always here
            const unsigned eo = (unsigned)(m - 1) * (IMG_W - 1);
            y1b[eo + co0]     = sgyP[0] - sgy[0];
            y1b[eo + co0 + 1] = sgyP[1] - sgy[1];
            y1b[eo + co1]     = sgyP[2] - sgy[2];
            if (!skip3) y1b[eo + co1 + 1] = sgyP[3] - sgy[3];
        }
        #pragma unroll
        for (int k = 0; k < 4; k++) {
            sgyP[k] = sgy[k];
            hdP2[k] = hdP1[k]; hdP1[k] = hd[k];
            hsP2[k] = hsP1[k]; hsP1[k] = hs[k];
        }
        hdRP2 = hdRP1; hdRP1 = hdR;
    }

    // ---- epilogue: y1 row r0+RS-1 needs gy at row r0+RS ----
    {
        const int m1 = r0 + RS - 1;
        if (m1 < IMG_H - 1) {
            RowVals rv = load_row(xb, r0 + RS + 1, lane, lane0, lane31, has_l, has_r);
            float hd[4], hs[4], hdR;
            row_combos(rv, lane0, lane31, hd, hs, hdR);
            const unsigned eo = (unsigned)m1 * (IMG_W - 1);
            const float s0 = fsign(hsP2[0] - hs[0]);
            const float s1 = fsign(hsP2[1] - hs[1]);
            const float s2 = fsign(hsP2[2] - hs[2]);
            const float s3 = fsign(hsP2[3] - hs[3]);
            y1b[eo + co0]     = sgyP[0] - s0;
            y1b[eo + co0 + 1] = sgyP[1] - s1;
            y1b[eo + co1]     = sgyP[2] - s2;
            if (!skip3) y1b[eo + co1 + 1] = sgyP[3] - s3;
        }
    }
}

extern "C" void kernel_launch(void* const* d_in, const int* in_sizes, int n_in,
                              void* d_out, int out_size) {
    const float* x = (const float*)d_in[0];
    const int B = in_sizes[0] / (IMG_H * IMG_W);

    float* y  = (float*)d_out;
    float* y0 = y  + (size_t)B * 2 * IMG_H * IMG_W;
    float* y1 = y0 + (size_t)B * (IMG_H - 1) * (IMG_W - 1);

    dim3 block(NT, 1, 1);
    dim3 grid(IMG_H / RS, 1, B);    // 32 row-bands x 16 batches = 512 blocks
    sobel_sign_kernel<<<grid, block>>>(x, y, y0, y1);
}